// round 1
// baseline (speedup 1.0000x reference)
#include <cuda_runtime.h>

#define BATCH 4
#define SEQ   2048
#define EMB   1024
#define NH    16
#define HD    64
#define MROWS (BATCH*SEQ)      // 8192
#define KDIM  EMB              // 1024

// Scratch: Q,K stored d-major [B,H,hd,T]; V row-major [B,H,T,hd]
__device__ float g_q[BATCH*NH*HD*SEQ];
__device__ float g_k[BATCH*NH*HD*SEQ];
__device__ float g_v[BATCH*NH*SEQ*HD];

// ---------------------------------------------------------------------------
// Kernel 1: qkv = x @ W^T + b, scattered into g_q/g_k/g_v layouts
// ---------------------------------------------------------------------------
#define BM  128
#define BN  128
#define BKK 16

__global__ void __launch_bounds__(256)
qkv_gemm_kernel(const float* __restrict__ x, const float* __restrict__ W,
                const float* __restrict__ bias) {
    __shared__ float As[BKK][BM];
    __shared__ float Bs[BKK][BN];

    const int tid = threadIdx.x;
    const int tx  = tid & 15;
    const int ty  = tid >> 4;
    const int m0  = blockIdx.y * BM;
    const int n0  = blockIdx.x * BN;

    const int lr = tid >> 2;           // 0..63
    const int lc = (tid & 3) << 2;     // 0,4,8,12

    const float* xp = x + (size_t)(m0 + lr) * KDIM + lc;
    const float* wp = W + (size_t)(n0 + lr) * KDIM + lc;

    float acc[8][8];
    #pragma unroll
    for (int i = 0; i < 8; i++)
        #pragma unroll
        for (int j = 0; j < 8; j++) acc[i][j] = 0.f;

    for (int kt = 0; kt < KDIM; kt += BKK) {
        #pragma unroll
        for (int p = 0; p < 2; p++) {
            float4 va = *(const float4*)(xp + (size_t)p*64*KDIM + kt);
            As[lc+0][lr + p*64] = va.x;
            As[lc+1][lr + p*64] = va.y;
            As[lc+2][lr + p*64] = va.z;
            As[lc+3][lr + p*64] = va.w;
            float4 vb = *(const float4*)(wp + (size_t)p*64*KDIM + kt);
            Bs[lc+0][lr + p*64] = vb.x;
            Bs[lc+1][lr + p*64] = vb.y;
            Bs[lc+2][lr + p*64] = vb.z;
            Bs[lc+3][lr + p*64] = vb.w;
        }
        __syncthreads();
        #pragma unroll
        for (int kk = 0; kk < BKK; kk++) {
            float a[8], b[8];
            *(float4*)&a[0] = *(const float4*)&As[kk][ty*8];
            *(float4*)&a[4] = *(const float4*)&As[kk][ty*8+4];
            *(float4*)&b[0] = *(const float4*)&Bs[kk][tx*8];
            *(float4*)&b[4] = *(const float4*)&Bs[kk][tx*8+4];
            #pragma unroll
            for (int i = 0; i < 8; i++)
                #pragma unroll
                for (int j = 0; j < 8; j++)
                    acc[i][j] += a[i]*b[j];
        }
        __syncthreads();
    }

    // Epilogue: add bias, scatter to scratch. Each 128-wide n-block lies
    // entirely inside one of q/k/v (EMB % BN == 0).
    const int which = n0 / EMB;              // 0=q 1=k 2=v
    const int cbase = (n0 % EMB) + tx*8;     // col within C at j=0
    const int h     = cbase >> 6;            // constant across j (cbase%64<=56)
    const int d0    = cbase & 63;
    const int mb    = m0 + ty*8;
    const int b     = mb / SEQ;              // constant across block rows used
    const int t     = mb % SEQ;

    #pragma unroll
    for (int j = 0; j < 8; j++) {
        const float bj = bias[n0 + tx*8 + j];
        #pragma unroll
        for (int i = 0; i < 8; i++) acc[i][j] += bj;
    }

    if (which == 2) {
        // V: [b,h,t,d] row-major
        float* vb = g_v + ((size_t)(b*NH + h)*SEQ + t)*HD + d0;
        #pragma unroll
        for (int i = 0; i < 8; i++) {
            float4 r0 = make_float4(acc[i][0], acc[i][1], acc[i][2], acc[i][3]);
            float4 r1 = make_float4(acc[i][4], acc[i][5], acc[i][6], acc[i][7]);
            *(float4*)(vb + (size_t)i*HD)     = r0;
            *(float4*)(vb + (size_t)i*HD + 4) = r1;
        }
    } else {
        // Q/K: [b,h,d,t] d-major — assemble float4 along t (i direction)
        float* qb   = (which == 0) ? g_q : g_k;
        float* base = qb + ((size_t)(b*NH + h)*HD + d0)*SEQ + t;
        #pragma unroll
        for (int j = 0; j < 8; j++) {
            float4 r0 = make_float4(acc[0][j], acc[1][j], acc[2][j], acc[3][j]);
            float4 r1 = make_float4(acc[4][j], acc[5][j], acc[6][j], acc[7][j]);
            *(float4*)(base + (size_t)j*SEQ)     = r0;
            *(float4*)(base + (size_t)j*SEQ + 4) = r1;
        }
    }
}

// ---------------------------------------------------------------------------
// Kernel 2: causal flash attention. One block = one (b,h) x 128-query tile.
// Q,K in smem d-major (no transpose needed thanks to scratch layout).
// ---------------------------------------------------------------------------
#define BQ  128
#define BKT 64
#define ATTN_SMEM ((64*128 + 64*64 + 64*64 + 64*129) * 4)

__global__ void __launch_bounds__(256)
attn_kernel(float* __restrict__ out) {
    extern __shared__ float smbuf[];
    float* Qs = smbuf;              // [64][128] d-major
    float* Ks = Qs + 64*128;        // [64][64]  d-major
    float* Vs = Ks + 64*64;         // [64][64]  k-major (row=key, col=d)
    float* Ps = Vs + 64*64;         // [64][129] k-major transposed P (pad)

    const int tid = threadIdx.x;
    const int tx  = tid & 15;       // 0..15 -> 4 keys / 4 d-cols
    const int ty  = tid >> 4;       // 0..15 -> 8 query rows
    const int bh  = blockIdx.y;     // 0..63
    const int q0  = blockIdx.x * BQ;

    const float* Qg = g_q + (size_t)bh*HD*SEQ;
    const float* Kg = g_k + (size_t)bh*HD*SEQ;
    const float* Vg = g_v + (size_t)bh*SEQ*HD;

    // Load Q tile [64 d][128 q]
    {
        const int r = tid >> 5;
        const int c = (tid & 31) << 2;
        #pragma unroll
        for (int p = 0; p < 8; p++)
            *(float4*)&Qs[(r + p*8)*128 + c] =
                *(const float4*)(Qg + (size_t)(r + p*8)*SEQ + q0 + c);
    }

    float m_i[8], l_i[8], o[8][4];
    #pragma unroll
    for (int i = 0; i < 8; i++) {
        m_i[i] = -1e30f; l_i[i] = 0.f;
        o[i][0] = o[i][1] = o[i][2] = o[i][3] = 0.f;
    }

    const int nkt = (q0 + BQ) / BKT;     // 2*qi + 2
    const int lr  = tid >> 4;            // 0..15
    const int lc  = (tid & 15) << 2;

    for (int kt = 0; kt < nkt; kt++) {
        const int k0 = kt * BKT;
        __syncthreads();   // prev iter done reading Ks/Vs
        #pragma unroll
        for (int p = 0; p < 4; p++) {
            *(float4*)&Ks[(lr + p*16)*64 + lc] =
                *(const float4*)(Kg + (size_t)(lr + p*16)*SEQ + k0 + lc);
            *(float4*)&Vs[(lr + p*16)*64 + lc] =
                *(const float4*)(Vg + (size_t)(k0 + lr + p*16)*HD + lc);
        }
        __syncthreads();

        // S = Q·K^T  (8 q-rows x 4 k-cols per thread)
        float s[8][4];
        #pragma unroll
        for (int i = 0; i < 8; i++)
            #pragma unroll
            for (int j = 0; j < 4; j++) s[i][j] = 0.f;

        #pragma unroll 8
        for (int d = 0; d < HD; d++) {
            float4 k4 = *(const float4*)&Ks[d*64 + tx*4];
            float4 qa = *(const float4*)&Qs[d*128 + ty*8];
            float4 qb = *(const float4*)&Qs[d*128 + ty*8 + 4];
            float q8[8] = {qa.x,qa.y,qa.z,qa.w,qb.x,qb.y,qb.z,qb.w};
            float kk[4] = {k4.x,k4.y,k4.z,k4.w};
            #pragma unroll
            for (int i = 0; i < 8; i++)
                #pragma unroll
                for (int j = 0; j < 4; j++)
                    s[i][j] += q8[i]*kk[j];
        }

        #pragma unroll
        for (int i = 0; i < 8; i++)
            #pragma unroll
            for (int j = 0; j < 4; j++) s[i][j] *= 0.125f;   // 1/sqrt(64)

        if (k0 + BKT - 1 > q0) {       // only the last two tiles need masking
            #pragma unroll
            for (int i = 0; i < 8; i++) {
                const int qg = q0 + ty*8 + i;
                #pragma unroll
                for (int j = 0; j < 4; j++)
                    if (k0 + tx*4 + j > qg) s[i][j] = -1e30f;
            }
        }

        // Online softmax, per row; reduce across the 16 tx lanes of the warp
        #pragma unroll
        for (int i = 0; i < 8; i++) {
            float rm = fmaxf(fmaxf(s[i][0], s[i][1]), fmaxf(s[i][2], s[i][3]));
            #pragma unroll
            for (int off = 8; off > 0; off >>= 1)
                rm = fmaxf(rm, __shfl_xor_sync(0xffffffffu, rm, off));
            const float mnew = fmaxf(m_i[i], rm);
            const float corr = __expf(m_i[i] - mnew);
            m_i[i] = mnew;
            float rs = 0.f;
            #pragma unroll
            for (int j = 0; j < 4; j++) {
                const float p = __expf(s[i][j] - mnew);
                s[i][j] = p;
                rs += p;
            }
            #pragma unroll
            for (int off = 8; off > 0; off >>= 1)
                rs += __shfl_xor_sync(0xffffffffu, rs, off);
            l_i[i] = l_i[i]*corr + rs;
            o[i][0] *= corr; o[i][1] *= corr; o[i][2] *= corr; o[i][3] *= corr;
            #pragma unroll
            for (int j = 0; j < 4; j++)
                Ps[(tx*4 + j)*129 + ty*8 + i] = s[i][j];
        }
        __syncthreads();

        // O += P·V
        #pragma unroll 4
        for (int k = 0; k < BKT; k++) {
            float4 v4 = *(const float4*)&Vs[k*64 + tx*4];
            #pragma unroll
            for (int i = 0; i < 8; i++) {
                const float p = Ps[k*129 + ty*8 + i];
                o[i][0] += p*v4.x;
                o[i][1] += p*v4.y;
                o[i][2] += p*v4.z;
                o[i][3] += p*v4.w;
            }
        }
    }

    // Normalize and write out [B,T,C]
    const int b = bh >> 4;
    const int h = bh & 15;
    float* op = out + ((size_t)b*SEQ + q0 + ty*8)*EMB + h*HD + tx*4;
    #pragma unroll
    for (int i = 0; i < 8; i++) {
        const float inv = 1.0f / l_i[i];
        float4 r = make_float4(o[i][0]*inv, o[i][1]*inv, o[i][2]*inv, o[i][3]*inv);
        *(float4*)(op + (size_t)i*EMB) = r;
    }
}

// ---------------------------------------------------------------------------
extern "C" void kernel_launch(void* const* d_in, const int* in_sizes, int n_in,
                              void* d_out, int out_size) {
    const float* x    = (const float*)d_in[0];
    const float* W    = (const float*)d_in[1];
    const float* bias = (const float*)d_in[2];
    float* out = (float*)d_out;

    cudaFuncSetAttribute(attn_kernel,
                         cudaFuncAttributeMaxDynamicSharedMemorySize, ATTN_SMEM);

    dim3 g1(3*EMB/BN, MROWS/BM);          // (24, 64)
    qkv_gemm_kernel<<<g1, 256>>>(x, W, bias);

    dim3 g2(SEQ/BQ, BATCH*NH);            // (16, 64)
    attn_kernel<<<g2, 256, ATTN_SMEM>>>(out);
}

// round 3
// speedup vs baseline: 2.7479x; 2.7479x over previous
#include <cuda_runtime.h>
#include <cstdint>

#define BATCH 4
#define SEQ   2048
#define EMB   1024
#define NH    16
#define HD    64
#define MROWS (BATCH*SEQ)
#define KDIM  EMB

// Scratch: Q,K stored d-major [B,H,hd,T]; V row-major [B,H,T,hd]
__device__ float g_q[BATCH*NH*HD*SEQ];
__device__ float g_k[BATCH*NH*HD*SEQ];
__device__ float g_v[BATCH*NH*SEQ*HD];

__device__ __forceinline__ unsigned tf32_of(float v) {
    unsigned r; asm("cvt.rna.tf32.f32 %0, %1;" : "=r"(r) : "f"(v)); return r;
}

// D += A(16x8,row) * B(8x8,col), tf32 inputs, fp32 accum
__device__ __forceinline__ void mma8(float* d, const unsigned* a, unsigned b0, unsigned b1) {
    asm volatile(
        "mma.sync.aligned.m16n8k8.row.col.f32.tf32.tf32.f32 "
        "{%0,%1,%2,%3}, {%4,%5,%6,%7}, {%8,%9}, {%0,%1,%2,%3};"
        : "+f"(d[0]), "+f"(d[1]), "+f"(d[2]), "+f"(d[3])
        : "r"(a[0]), "r"(a[1]), "r"(a[2]), "r"(a[3]), "r"(b0), "r"(b1));
}

// ---------------------------------------------------------------------------
// Kernel 1: qkv = x @ W^T + b  (tf32 mma), scatter into g_q/g_k/g_v
// ---------------------------------------------------------------------------
#define GBM 128
#define GBN 128
#define GBK 32
#define GPAD 36
#define GEMM_SMEM (2*(GBM + GBN)*GPAD*4)

__global__ void __launch_bounds__(256, 1)
qkv_gemm_mma(const float* __restrict__ x, const float* __restrict__ W,
             const float* __restrict__ bias) {
    extern __shared__ unsigned gsm[];
    unsigned* As = gsm;                       // [2][GBM*GPAD]
    unsigned* Bs = gsm + 2*GBM*GPAD;          // [2][GBN*GPAD]

    const int tid  = threadIdx.x;
    const int lane = tid & 31;
    const int warp = tid >> 5;
    const int g    = lane >> 2;
    const int t4   = lane & 3;
    const int wm   = warp >> 1;               // 0..3
    const int wn   = warp & 1;                // 0..1
    const int m0   = blockIdx.y * GBM;
    const int n0   = blockIdx.x * GBN;

    const int crow = tid >> 3;                // 0..31
    const int ccol = (tid & 7) * 4;           // 0..28

    const float* xp = x + (size_t)m0 * KDIM;
    const float* wp = W + (size_t)n0 * KDIM;

    float acc[2][8][4];
    #pragma unroll
    for (int mt = 0; mt < 2; mt++)
        #pragma unroll
        for (int nt = 0; nt < 8; nt++)
            #pragma unroll
            for (int r = 0; r < 4; r++) acc[mt][nt][r] = 0.f;

    float4 fa[4], fb[4];

    // prologue load (kt=0)
    #pragma unroll
    for (int p = 0; p < 4; p++) {
        int row = crow + p*32;
        fa[p] = *(const float4*)(xp + (size_t)row*KDIM + ccol);
        fb[p] = *(const float4*)(wp + (size_t)row*KDIM + ccol);
    }
    #pragma unroll
    for (int p = 0; p < 4; p++) {
        int row = crow + p*32;
        *(uint4*)&As[row*GPAD + ccol] = make_uint4(tf32_of(fa[p].x), tf32_of(fa[p].y), tf32_of(fa[p].z), tf32_of(fa[p].w));
        *(uint4*)&Bs[row*GPAD + ccol] = make_uint4(tf32_of(fb[p].x), tf32_of(fb[p].y), tf32_of(fb[p].z), tf32_of(fb[p].w));
    }
    __syncthreads();

    const int NK = KDIM / GBK;                // 32
    for (int kt = 0; kt < NK; kt++) {
        if (kt + 1 < NK) {
            const int ko = (kt + 1) * GBK;
            #pragma unroll
            for (int p = 0; p < 4; p++) {
                int row = crow + p*32;
                fa[p] = *(const float4*)(xp + (size_t)row*KDIM + ko + ccol);
                fb[p] = *(const float4*)(wp + (size_t)row*KDIM + ko + ccol);
            }
        }
        // compute on buffer kt&1
        {
            const unsigned* Ab = As + (kt & 1)*GBM*GPAD + (wm*32)*GPAD;
            const unsigned* Bb = Bs + (kt & 1)*GBN*GPAD + (wn*64)*GPAD;
            #pragma unroll
            for (int ks = 0; ks < 4; ks++) {
                const int k0 = ks * 8;
                unsigned a[2][4], b[8][2];
                #pragma unroll
                for (int mt = 0; mt < 2; mt++) {
                    a[mt][0] = Ab[(mt*16 + g    )*GPAD + k0 + t4];
                    a[mt][1] = Ab[(mt*16 + g + 8)*GPAD + k0 + t4];
                    a[mt][2] = Ab[(mt*16 + g    )*GPAD + k0 + t4 + 4];
                    a[mt][3] = Ab[(mt*16 + g + 8)*GPAD + k0 + t4 + 4];
                }
                #pragma unroll
                for (int nt = 0; nt < 8; nt++) {
                    b[nt][0] = Bb[(nt*8 + g)*GPAD + k0 + t4];
                    b[nt][1] = Bb[(nt*8 + g)*GPAD + k0 + t4 + 4];
                }
                #pragma unroll
                for (int mt = 0; mt < 2; mt++)
                    #pragma unroll
                    for (int nt = 0; nt < 8; nt++)
                        mma8(acc[mt][nt], a[mt], b[nt][0], b[nt][1]);
            }
        }
        if (kt + 1 < NK) {
            unsigned* Ab = As + ((kt + 1) & 1)*GBM*GPAD;
            unsigned* Bb = Bs + ((kt + 1) & 1)*GBN*GPAD;
            #pragma unroll
            for (int p = 0; p < 4; p++) {
                int row = crow + p*32;
                *(uint4*)&Ab[row*GPAD + ccol] = make_uint4(tf32_of(fa[p].x), tf32_of(fa[p].y), tf32_of(fa[p].z), tf32_of(fa[p].w));
                *(uint4*)&Bb[row*GPAD + ccol] = make_uint4(tf32_of(fb[p].x), tf32_of(fb[p].y), tf32_of(fb[p].z), tf32_of(fb[p].w));
            }
            __syncthreads();
        }
    }

    // Epilogue: bias + scatter. n-block fully within one of q/k/v.
    const int which = n0 / EMB;               // 0=q 1=k 2=v
    const int b     = m0 / SEQ;
    #pragma unroll
    for (int nt = 0; nt < 8; nt++) {
        const int col = n0 + wn*64 + nt*8 + 2*t4;
        const float b0v = bias[col];
        const float b1v = bias[col + 1];
        const int c = col % EMB;
        const int h = c >> 6;
        const int d = c & 63;
        #pragma unroll
        for (int mt = 0; mt < 2; mt++) {
            #pragma unroll
            for (int rr = 0; rr < 2; rr++) {
                const int m = m0 + wm*32 + mt*16 + g + rr*8;
                const int t = m % SEQ;
                const float v0 = acc[mt][nt][rr*2 + 0] + b0v;
                const float v1 = acc[mt][nt][rr*2 + 1] + b1v;
                if (which == 2) {
                    *(float2*)&g_v[((size_t)(b*NH + h)*SEQ + t)*HD + d] = make_float2(v0, v1);
                } else {
                    float* base = (which == 0 ? g_q : g_k) + ((size_t)(b*NH + h)*HD + d)*SEQ + t;
                    base[0]   = v0;
                    base[SEQ] = v1;   // next d, same t
                }
            }
        }
    }
}

// ---------------------------------------------------------------------------
// Kernel 2: causal flash attention, tf32 mma. BQ=128 (8 warps), BKT=64.
// ---------------------------------------------------------------------------
#define APAD 72
#define QPAD 136
#define ATT_SMEM ((64*APAD + 64*APAD + 128*APAD)*4)

__global__ void __launch_bounds__(256, 1)
attn_mma(float* __restrict__ out) {
    extern __shared__ unsigned asm_[];
    unsigned* Ks = asm_;                      // [64 d][APAD]  (d-major)
    unsigned* Vs = asm_ + 64*APAD;            // [64 key][APAD]
    unsigned* Ps = asm_ + 2*64*APAD;          // [128 q][APAD]; also Q staging [64 d][QPAD]

    const int tid  = threadIdx.x;
    const int lane = tid & 31;
    const int w    = tid >> 5;                // 0..7
    const int g    = lane >> 2;
    const int t4   = lane & 3;
    const int qi   = gridDim.x - 1 - blockIdx.x;   // heavy tiles first
    const int q0   = qi * 128;
    const int bh   = blockIdx.y;

    const float* Qg = g_q + (size_t)bh*HD*SEQ;
    const float* Kg = g_k + (size_t)bh*HD*SEQ;
    const float* Vg = g_v + (size_t)bh*SEQ*HD;

    // Stage Q (pre-scaled by 1/sqrt(64)) into Ps as Qs[d][q], pad QPAD
    #pragma unroll
    for (int p = 0; p < 8; p++) {
        const int id = tid + p*256;
        const int d  = id >> 5;
        const int qc = (id & 31) * 4;
        float4 v = *(const float4*)(Qg + (size_t)d*SEQ + q0 + qc);
        *(uint4*)&Ps[d*QPAD + qc] = make_uint4(
            tf32_of(v.x*0.125f), tf32_of(v.y*0.125f),
            tf32_of(v.z*0.125f), tf32_of(v.w*0.125f));
    }
    __syncthreads();

    // Q A-fragments: 16 rows per warp, K=64 -> 8 k-steps
    unsigned qa[8][4];
    #pragma unroll
    for (int kk = 0; kk < 8; kk++) {
        const int r = kk*8 + t4;
        qa[kk][0] = Ps[(r    )*QPAD + w*16 + g];
        qa[kk][1] = Ps[(r    )*QPAD + w*16 + g + 8];
        qa[kk][2] = Ps[(r + 4)*QPAD + w*16 + g];
        qa[kk][3] = Ps[(r + 4)*QPAD + w*16 + g + 8];
    }

    float o[8][4];
    #pragma unroll
    for (int nt = 0; nt < 8; nt++)
        #pragma unroll
        for (int r = 0; r < 4; r++) o[nt][r] = 0.f;
    float m0r = -1e30f, m1r = -1e30f, l0 = 0.f, l1 = 0.f;

    const int row0 = q0 + w*16 + g;           // this thread's low row
    const int nkt  = 2*qi + 2;

    for (int kt = 0; kt < nkt; kt++) {
        const int k0 = kt * 64;
        __syncthreads();
        // stage K [d][key] and V [key][d]
        #pragma unroll
        for (int p = 0; p < 4; p++) {
            const int id = tid + p*256;
            const int r  = id >> 4;
            const int c  = (id & 15) * 4;
            float4 kv = *(const float4*)(Kg + (size_t)r*SEQ + k0 + c);
            *(uint4*)&Ks[r*APAD + c] = make_uint4(tf32_of(kv.x), tf32_of(kv.y), tf32_of(kv.z), tf32_of(kv.w));
            float4 vv = *(const float4*)(Vg + (size_t)(k0 + r)*HD + c);
            *(uint4*)&Vs[r*APAD + c] = make_uint4(tf32_of(vv.x), tf32_of(vv.y), tf32_of(vv.z), tf32_of(vv.w));
        }
        __syncthreads();

        // warp fully above the diagonal for this tile? -> contributes nothing
        if (k0 > q0 + w*16 + 15) continue;

        // S = Q K^T
        float s[8][4];
        #pragma unroll
        for (int nt = 0; nt < 8; nt++)
            #pragma unroll
            for (int r = 0; r < 4; r++) s[nt][r] = 0.f;
        #pragma unroll
        for (int kk = 0; kk < 8; kk++) {
            const int r = kk*8 + t4;
            #pragma unroll
            for (int nt = 0; nt < 8; nt++) {
                unsigned b0 = Ks[(r    )*APAD + nt*8 + g];
                unsigned b1 = Ks[(r + 4)*APAD + nt*8 + g];
                mma8(s[nt], qa[kk], b0, b1);
            }
        }

        // causal mask — needed iff tile end exceeds the warp's FIRST row
        // (R2 bug: compared against last row, leaking future keys for the
        //  tile whose end coincides with the warp's row span)
        if (k0 + 63 > q0 + w*16) {
            #pragma unroll
            for (int nt = 0; nt < 8; nt++) {
                const int col = k0 + nt*8 + 2*t4;
                if (col     > row0    ) s[nt][0] = -1e30f;
                if (col + 1 > row0    ) s[nt][1] = -1e30f;
                if (col     > row0 + 8) s[nt][2] = -1e30f;
                if (col + 1 > row0 + 8) s[nt][3] = -1e30f;
            }
        }

        // online softmax (rows g and g+8 of this warp's 16)
        float mx0 = -1e30f, mx1 = -1e30f;
        #pragma unroll
        for (int nt = 0; nt < 8; nt++) {
            mx0 = fmaxf(mx0, fmaxf(s[nt][0], s[nt][1]));
            mx1 = fmaxf(mx1, fmaxf(s[nt][2], s[nt][3]));
        }
        mx0 = fmaxf(mx0, __shfl_xor_sync(0xffffffffu, mx0, 1));
        mx0 = fmaxf(mx0, __shfl_xor_sync(0xffffffffu, mx0, 2));
        mx1 = fmaxf(mx1, __shfl_xor_sync(0xffffffffu, mx1, 1));
        mx1 = fmaxf(mx1, __shfl_xor_sync(0xffffffffu, mx1, 2));
        const float mn0 = fmaxf(m0r, mx0);
        const float mn1 = fmaxf(m1r, mx1);
        const float c0  = __expf(m0r - mn0);
        const float c1  = __expf(m1r - mn1);
        m0r = mn0; m1r = mn1;

        float sum0 = 0.f, sum1 = 0.f;
        #pragma unroll
        for (int nt = 0; nt < 8; nt++) {
            const float p00 = __expf(s[nt][0] - mn0);
            const float p01 = __expf(s[nt][1] - mn0);
            const float p10 = __expf(s[nt][2] - mn1);
            const float p11 = __expf(s[nt][3] - mn1);
            sum0 += p00 + p01;
            sum1 += p10 + p11;
            const int pc = nt*8 + 2*t4;
            *(uint2*)&Ps[(w*16 + g    )*APAD + pc] = make_uint2(tf32_of(p00), tf32_of(p01));
            *(uint2*)&Ps[(w*16 + g + 8)*APAD + pc] = make_uint2(tf32_of(p10), tf32_of(p11));
        }
        sum0 += __shfl_xor_sync(0xffffffffu, sum0, 1);
        sum0 += __shfl_xor_sync(0xffffffffu, sum0, 2);
        sum1 += __shfl_xor_sync(0xffffffffu, sum1, 1);
        sum1 += __shfl_xor_sync(0xffffffffu, sum1, 2);
        l0 = l0*c0 + sum0;
        l1 = l1*c1 + sum1;
        #pragma unroll
        for (int nt = 0; nt < 8; nt++) {
            o[nt][0] *= c0; o[nt][1] *= c0;
            o[nt][2] *= c1; o[nt][3] *= c1;
        }
        __syncwarp();

        // O += P V
        #pragma unroll
        for (int kk = 0; kk < 8; kk++) {
            unsigned pa[4];
            const int pr = (w*16 + g)*APAD + kk*8 + t4;
            pa[0] = Ps[pr];
            pa[1] = Ps[pr + 8*APAD];
            pa[2] = Ps[pr + 4];
            pa[3] = Ps[pr + 8*APAD + 4];
            const int vr = kk*8 + t4;
            #pragma unroll
            for (int nt = 0; nt < 8; nt++) {
                unsigned b0 = Vs[(vr    )*APAD + nt*8 + g];
                unsigned b1 = Vs[(vr + 4)*APAD + nt*8 + g];
                mma8(o[nt], pa, b0, b1);
            }
        }
        __syncwarp();   // P reads done before next tile's P writes
    }

    // epilogue: out[b, t, h*64 + d]
    const int bb = bh >> 4;
    const int h  = bh & 15;
    const float inv0 = 1.f / l0;
    const float inv1 = 1.f / l1;
    float* op = out + ((size_t)bb*SEQ + row0)*EMB + h*HD;
    #pragma unroll
    for (int nt = 0; nt < 8; nt++) {
        const int d = nt*8 + 2*t4;
        *(float2*)(op + d)              = make_float2(o[nt][0]*inv0, o[nt][1]*inv0);
        *(float2*)(op + 8*EMB + d)      = make_float2(o[nt][2]*inv1, o[nt][3]*inv1);
    }
}

// ---------------------------------------------------------------------------
extern "C" void kernel_launch(void* const* d_in, const int* in_sizes, int n_in,
                              void* d_out, int out_size) {
    const float* x    = (const float*)d_in[0];
    const float* W    = (const float*)d_in[1];
    const float* bias = (const float*)d_in[2];
    float* out = (float*)d_out;

    cudaFuncSetAttribute(qkv_gemm_mma, cudaFuncAttributeMaxDynamicSharedMemorySize, GEMM_SMEM);
    cudaFuncSetAttribute(attn_mma,     cudaFuncAttributeMaxDynamicSharedMemorySize, ATT_SMEM);

    dim3 g1(3*EMB/GBN, MROWS/GBM);            // (24, 64)
    qkv_gemm_mma<<<g1, 256, GEMM_SMEM>>>(x, W, bias);

    dim3 g2(SEQ/128, BATCH*NH);               // (16, 64)
    attn_mma<<<g2, 256, ATT_SMEM>>>(out);
}

// round 4
// speedup vs baseline: 3.4666x; 1.2616x over previous
#include <cuda_runtime.h>
#include <cstdint>

#define BATCH 4
#define SEQ   2048
#define EMB   1024
#define NH    16
#define HD    64
#define MROWS (BATCH*SEQ)
#define KDIM  EMB

// Scratch: Q,K row-major [B,H,T,hd]; V d-major [B,H,hd,T]
__device__ float g_q[BATCH*NH*SEQ*HD];
__device__ float g_k[BATCH*NH*SEQ*HD];
__device__ float g_v[BATCH*NH*HD*SEQ];

__device__ __forceinline__ unsigned tf32_of(float v) {
    unsigned r; asm("cvt.rna.tf32.f32 %0, %1;" : "=r"(r) : "f"(v)); return r;
}

__device__ __forceinline__ void mma8(float* d, const unsigned* a, unsigned b0, unsigned b1) {
    asm volatile(
        "mma.sync.aligned.m16n8k8.row.col.f32.tf32.tf32.f32 "
        "{%0,%1,%2,%3}, {%4,%5,%6,%7}, {%8,%9}, {%0,%1,%2,%3};"
        : "+f"(d[0]), "+f"(d[1]), "+f"(d[2]), "+f"(d[3])
        : "r"(a[0]), "r"(a[1]), "r"(a[2]), "r"(a[3]), "r"(b0), "r"(b1));
}

// ldmatrix x4: 4 tiles of 8 rows x 16B; thread t of tile m holds b32 elem
// (row t%... ) -> (r=lane/4, c=lane%4) per tile. addr = per-thread row ptr.
__device__ __forceinline__ uint4 ldmx4(unsigned addr) {
    uint4 r;
    asm volatile("ldmatrix.sync.aligned.m8n8.x4.shared.b16 {%0,%1,%2,%3}, [%4];"
        : "=r"(r.x), "=r"(r.y), "=r"(r.z), "=r"(r.w) : "r"(addr));
    return r;
}

// ---------------------------------------------------------------------------
// Kernel 1: qkv = x @ W^T + b  (tf32 mma + ldmatrix), scatter to scratch
// ---------------------------------------------------------------------------
#define GBM 128
#define GBN 128
#define GBK 32
#define GPAD 36
#define GEMM_SMEM (2*(GBM + GBN)*GPAD*4)

__global__ void __launch_bounds__(256, 2)
qkv_gemm_mma(const float* __restrict__ x, const float* __restrict__ W,
             const float* __restrict__ bias) {
    extern __shared__ unsigned gsm[];
    unsigned* As = gsm;                       // [2][GBM*GPAD], m-major
    unsigned* Bs = gsm + 2*GBM*GPAD;          // [2][GBN*GPAD], n-major

    const int tid  = threadIdx.x;
    const int lane = tid & 31;
    const int warp = tid >> 5;
    const int g    = lane >> 2;
    const int t4   = lane & 3;
    const int wm   = warp >> 1;               // 0..3
    const int wn   = warp & 1;                // 0..1
    const int m0   = blockIdx.y * GBM;
    const int n0   = blockIdx.x * GBN;

    const int crow = tid >> 3;                // 0..31
    const int ccol = (tid & 7) * 4;           // 0..28

    const float* xp = x + (size_t)m0 * KDIM;
    const float* wp = W + (size_t)n0 * KDIM;

    // ldmatrix per-thread base offsets (A pattern / B pattern)
    const int arow = ((lane >> 3) & 1)*8 + (lane & 7);
    const int acol = (lane >> 4) * 4;
    const int brow = (lane >> 4)*8 + (lane & 7);
    const int bcol = ((lane >> 3) & 1) * 4;
    const unsigned aBase = (unsigned)__cvta_generic_to_shared(As)
                         + ((wm*32 + arow)*GPAD + acol)*4;
    const unsigned bBase = (unsigned)__cvta_generic_to_shared(Bs)
                         + ((wn*64 + brow)*GPAD + bcol)*4;

    float acc[2][8][4];
    #pragma unroll
    for (int mt = 0; mt < 2; mt++)
        #pragma unroll
        for (int nt = 0; nt < 8; nt++)
            #pragma unroll
            for (int r = 0; r < 4; r++) acc[mt][nt][r] = 0.f;

    float4 fa[4], fb[4];

    #pragma unroll
    for (int p = 0; p < 4; p++) {
        int row = crow + p*32;
        fa[p] = *(const float4*)(xp + (size_t)row*KDIM + ccol);
        fb[p] = *(const float4*)(wp + (size_t)row*KDIM + ccol);
    }
    #pragma unroll
    for (int p = 0; p < 4; p++) {
        int row = crow + p*32;
        *(uint4*)&As[row*GPAD + ccol] = make_uint4(tf32_of(fa[p].x), tf32_of(fa[p].y), tf32_of(fa[p].z), tf32_of(fa[p].w));
        *(uint4*)&Bs[row*GPAD + ccol] = make_uint4(tf32_of(fb[p].x), tf32_of(fb[p].y), tf32_of(fb[p].z), tf32_of(fb[p].w));
    }
    __syncthreads();

    const int NK = KDIM / GBK;                // 32
    for (int kt = 0; kt < NK; kt++) {
        if (kt + 1 < NK) {
            const int ko = (kt + 1) * GBK;
            #pragma unroll
            for (int p = 0; p < 4; p++) {
                int row = crow + p*32;
                fa[p] = *(const float4*)(xp + (size_t)row*KDIM + ko + ccol);
                fb[p] = *(const float4*)(wp + (size_t)row*KDIM + ko + ccol);
            }
        }
        {
            const unsigned abuf = aBase + (kt & 1)*GBM*GPAD*4;
            const unsigned bbuf = bBase + (kt & 1)*GBN*GPAD*4;
            #pragma unroll
            for (int ks = 0; ks < 4; ks++) {
                const int k0 = ks * 8;
                uint4 af0 = ldmx4(abuf + k0*4);
                uint4 af1 = ldmx4(abuf + (16*GPAD + k0)*4);
                #pragma unroll
                for (int j = 0; j < 4; j++) {
                    uint4 bf = ldmx4(bbuf + (j*16*GPAD + k0)*4);
                    mma8(acc[0][2*j],   &af0.x, bf.x, bf.y);
                    mma8(acc[0][2*j+1], &af0.x, bf.z, bf.w);
                    mma8(acc[1][2*j],   &af1.x, bf.x, bf.y);
                    mma8(acc[1][2*j+1], &af1.x, bf.z, bf.w);
                }
            }
        }
        if (kt + 1 < NK) {
            unsigned* Ab = As + ((kt + 1) & 1)*GBM*GPAD;
            unsigned* Bb = Bs + ((kt + 1) & 1)*GBN*GPAD;
            #pragma unroll
            for (int p = 0; p < 4; p++) {
                int row = crow + p*32;
                *(uint4*)&Ab[row*GPAD + ccol] = make_uint4(tf32_of(fa[p].x), tf32_of(fa[p].y), tf32_of(fa[p].z), tf32_of(fa[p].w));
                *(uint4*)&Bb[row*GPAD + ccol] = make_uint4(tf32_of(fb[p].x), tf32_of(fb[p].y), tf32_of(fb[p].z), tf32_of(fb[p].w));
            }
            __syncthreads();
        }
    }

    // Epilogue. Q,K row-major [b,h,t,d]; V d-major [b,h,d,t].
    const int which = n0 / EMB;               // 0=q 1=k 2=v
    const int b     = m0 / SEQ;
    #pragma unroll
    for (int nt = 0; nt < 8; nt++) {
        const int col = n0 + wn*64 + nt*8 + 2*t4;
        const float b0v = bias[col];
        const float b1v = bias[col + 1];
        const int c = col % EMB;
        const int h = c >> 6;
        const int d = c & 63;
        #pragma unroll
        for (int mt = 0; mt < 2; mt++) {
            #pragma unroll
            for (int rr = 0; rr < 2; rr++) {
                const int m = m0 + wm*32 + mt*16 + g + rr*8;
                const int t = m % SEQ;
                const float v0 = acc[mt][nt][rr*2 + 0] + b0v;
                const float v1 = acc[mt][nt][rr*2 + 1] + b1v;
                if (which == 2) {
                    float* base = g_v + ((size_t)(b*NH + h)*HD + d)*SEQ + t;
                    base[0]   = v0;
                    base[SEQ] = v1;          // next d, same t
                } else {
                    float* qk = (which == 0 ? g_q : g_k);
                    *(float2*)&qk[((size_t)(b*NH + h)*SEQ + t)*HD + d] = make_float2(v0, v1);
                }
            }
        }
    }
}

// ---------------------------------------------------------------------------
// Kernel 2: causal flash attention, tf32 mma + ldmatrix. BQ=128, BKT=64.
// ---------------------------------------------------------------------------
#define KP 68
#define ATT_SMEM ((128*KP + 64*KP + 64*KP + 128*KP)*4)   // Qs,Ks,Vs,Ps

__global__ void __launch_bounds__(256, 2)
attn_mma(float* __restrict__ out) {
    extern __shared__ unsigned asm_[];
    unsigned* Qs = asm_;                      // [128 q][KP d]   q-major
    unsigned* Ks = Qs + 128*KP;               // [64 key][KP d]  key-major
    unsigned* Vs = Ks + 64*KP;                // [64 d][KP key]  d-major
    unsigned* Ps = Vs + 64*KP;                // [128 q][KP key] q-major

    const int tid  = threadIdx.x;
    const int lane = tid & 31;
    const int w    = tid >> 5;                // 0..7
    const int g    = lane >> 2;
    const int t4   = lane & 3;
    const int qi   = gridDim.x - 1 - blockIdx.x;   // heavy tiles first
    const int q0   = qi * 128;
    const int bh   = blockIdx.y;

    const float* Qg = g_q + ((size_t)bh*SEQ + q0)*HD;   // rows q0..q0+127
    const float* Kg = g_k + (size_t)bh*SEQ*HD;          // [t][d]
    const float* Vg = g_v + (size_t)bh*HD*SEQ;          // [d][t]

    // ldmatrix per-thread offsets
    const int arow = ((lane >> 3) & 1)*8 + (lane & 7);  // A pattern rows
    const int acol = (lane >> 4) * 4;
    const int brow = lane & 7;                          // B pattern (attn)
    const int bcol = (lane >> 3) * 4;
    const unsigned qBase = (unsigned)__cvta_generic_to_shared(Qs) + ((w*16 + arow)*KP + acol)*4;
    const unsigned pBase = (unsigned)__cvta_generic_to_shared(Ps) + ((w*16 + arow)*KP + acol)*4;
    const unsigned kBase = (unsigned)__cvta_generic_to_shared(Ks) + (brow*KP + bcol)*4;
    const unsigned vBase = (unsigned)__cvta_generic_to_shared(Vs) + (brow*KP + bcol)*4;

    // Stage Q (pre-scaled) q-major
    #pragma unroll
    for (int p = 0; p < 8; p++) {
        const int id = tid + p*256;
        const int r  = id >> 4;
        const int c  = (id & 15) * 4;
        float4 v = *(const float4*)(Qg + (size_t)r*HD + c);
        *(uint4*)&Qs[r*KP + c] = make_uint4(
            tf32_of(v.x*0.125f), tf32_of(v.y*0.125f),
            tf32_of(v.z*0.125f), tf32_of(v.w*0.125f));
    }

    float o[8][4];
    #pragma unroll
    for (int nt = 0; nt < 8; nt++)
        #pragma unroll
        for (int r = 0; r < 4; r++) o[nt][r] = 0.f;
    float m0r = -1e30f, m1r = -1e30f, l0 = 0.f, l1 = 0.f;

    const int row0 = q0 + w*16 + g;
    const int nkt  = 2*qi + 2;

    for (int kt = 0; kt < nkt; kt++) {
        const int k0 = kt * 64;
        __syncthreads();   // prev tile readers done (also covers Q staging on kt=0)
        #pragma unroll
        for (int p = 0; p < 4; p++) {
            const int id = tid + p*256;
            const int r  = id >> 4;
            const int c  = (id & 15) * 4;
            float4 kv = *(const float4*)(Kg + (size_t)(k0 + r)*HD + c);   // key-major
            *(uint4*)&Ks[r*KP + c] = make_uint4(tf32_of(kv.x), tf32_of(kv.y), tf32_of(kv.z), tf32_of(kv.w));
            float4 vv = *(const float4*)(Vg + (size_t)r*SEQ + k0 + c);    // d-major
            *(uint4*)&Vs[r*KP + c] = make_uint4(tf32_of(vv.x), tf32_of(vv.y), tf32_of(vv.z), tf32_of(vv.w));
        }
        __syncthreads();

        if (k0 > q0 + w*16 + 15) continue;   // warp fully above diagonal

        // S = Q K^T
        float s[8][4];
        #pragma unroll
        for (int nt = 0; nt < 8; nt++)
            #pragma unroll
            for (int r = 0; r < 4; r++) s[nt][r] = 0.f;
        #pragma unroll
        for (int kkp = 0; kkp < 4; kkp++) {
            const int kk = kkp*2;
            uint4 qa0 = ldmx4(qBase + (kk*8)*4);
            uint4 qa1 = ldmx4(qBase + (kk*8 + 8)*4);
            #pragma unroll
            for (int nt = 0; nt < 8; nt++) {
                uint4 kb = ldmx4(kBase + (nt*8*KP + kk*8)*4);
                mma8(s[nt], &qa0.x, kb.x, kb.y);
                mma8(s[nt], &qa1.x, kb.z, kb.w);
            }
        }

        // causal mask: needed iff tile end exceeds warp's first row
        if (k0 + 63 > q0 + w*16) {
            #pragma unroll
            for (int nt = 0; nt < 8; nt++) {
                const int col = k0 + nt*8 + 2*t4;
                if (col     > row0    ) s[nt][0] = -1e30f;
                if (col + 1 > row0    ) s[nt][1] = -1e30f;
                if (col     > row0 + 8) s[nt][2] = -1e30f;
                if (col + 1 > row0 + 8) s[nt][3] = -1e30f;
            }
        }

        // online softmax
        float mx0 = -1e30f, mx1 = -1e30f;
        #pragma unroll
        for (int nt = 0; nt < 8; nt++) {
            mx0 = fmaxf(mx0, fmaxf(s[nt][0], s[nt][1]));
            mx1 = fmaxf(mx1, fmaxf(s[nt][2], s[nt][3]));
        }
        mx0 = fmaxf(mx0, __shfl_xor_sync(0xffffffffu, mx0, 1));
        mx0 = fmaxf(mx0, __shfl_xor_sync(0xffffffffu, mx0, 2));
        mx1 = fmaxf(mx1, __shfl_xor_sync(0xffffffffu, mx1, 1));
        mx1 = fmaxf(mx1, __shfl_xor_sync(0xffffffffu, mx1, 2));
        const float mn0 = fmaxf(m0r, mx0);
        const float mn1 = fmaxf(m1r, mx1);
        const float c0  = __expf(m0r - mn0);
        const float c1  = __expf(m1r - mn1);
        m0r = mn0; m1r = mn1;

        float sum0 = 0.f, sum1 = 0.f;
        #pragma unroll
        for (int nt = 0; nt < 8; nt++) {
            const float p00 = __expf(s[nt][0] - mn0);
            const float p01 = __expf(s[nt][1] - mn0);
            const float p10 = __expf(s[nt][2] - mn1);
            const float p11 = __expf(s[nt][3] - mn1);
            sum0 += p00 + p01;
            sum1 += p10 + p11;
            const int pc = nt*8 + 2*t4;
            *(uint2*)&Ps[(w*16 + g    )*KP + pc] = make_uint2(tf32_of(p00), tf32_of(p01));
            *(uint2*)&Ps[(w*16 + g + 8)*KP + pc] = make_uint2(tf32_of(p10), tf32_of(p11));
        }
        sum0 += __shfl_xor_sync(0xffffffffu, sum0, 1);
        sum0 += __shfl_xor_sync(0xffffffffu, sum0, 2);
        sum1 += __shfl_xor_sync(0xffffffffu, sum1, 1);
        sum1 += __shfl_xor_sync(0xffffffffu, sum1, 2);
        l0 = l0*c0 + sum0;
        l1 = l1*c1 + sum1;
        #pragma unroll
        for (int nt = 0; nt < 8; nt++) {
            o[nt][0] *= c0; o[nt][1] *= c0;
            o[nt][2] *= c1; o[nt][3] *= c1;
        }
        __syncwarp();   // P writes visible to warp's ldmatrix

        // O += P V
        #pragma unroll
        for (int kkp = 0; kkp < 4; kkp++) {
            const int kk = kkp*2;
            uint4 pa0 = ldmx4(pBase + (kk*8)*4);
            uint4 pa1 = ldmx4(pBase + (kk*8 + 8)*4);
            #pragma unroll
            for (int nt = 0; nt < 8; nt++) {
                uint4 vb = ldmx4(vBase + (nt*8*KP + kk*8)*4);
                mma8(o[nt], &pa0.x, vb.x, vb.y);
                mma8(o[nt], &pa1.x, vb.z, vb.w);
            }
        }
        __syncwarp();   // P reads done before next tile's writes
    }

    const int bb = bh >> 4;
    const int h  = bh & 15;
    const float inv0 = 1.f / l0;
    const float inv1 = 1.f / l1;
    float* op = out + ((size_t)bb*SEQ + row0)*EMB + h*HD;
    #pragma unroll
    for (int nt = 0; nt < 8; nt++) {
        const int d = nt*8 + 2*t4;
        *(float2*)(op + d)         = make_float2(o[nt][0]*inv0, o[nt][1]*inv0);
        *(float2*)(op + 8*EMB + d) = make_float2(o[nt][2]*inv1, o[nt][3]*inv1);
    }
}

// ---------------------------------------------------------------------------
extern "C" void kernel_launch(void* const* d_in, const int* in_sizes, int n_in,
                              void* d_out, int out_size) {
    const float* x    = (const float*)d_in[0];
    const float* W    = (const float*)d_in[1];
    const float* bias = (const float*)d_in[2];
    float* out = (float*)d_out;

    cudaFuncSetAttribute(qkv_gemm_mma, cudaFuncAttributeMaxDynamicSharedMemorySize, GEMM_SMEM);
    cudaFuncSetAttribute(attn_mma,     cudaFuncAttributeMaxDynamicSharedMemorySize, ATT_SMEM);

    dim3 g1(3*EMB/GBN, MROWS/GBM);            // (24, 64)
    qkv_gemm_mma<<<g1, 256, GEMM_SMEM>>>(x, W, bias);

    dim3 g2(SEQ/128, BATCH*NH);               // (16, 64)
    attn_mma<<<g2, 256, ATT_SMEM>>>(out);
}